// round 1
// baseline (speedup 1.0000x reference)
#include <cuda_runtime.h>
#include <math.h>

#define Nn 8
#define Tt 64
#define Aa 65536
#define Cc 80
#define NFLT4 (Aa * (Cc / 4))          // float4s of y_pred per batch image = 1,310,720
#define K4_BLOCKS_X (NFLT4 / 256)      // 5120
#define NBLK (K4_BLOCKS_X * Nn)        // 40960

#define F_ALPHA 0.25f
#define F_EPS 1e-6f
#define SL1_BETA (1.0f / 9.0f)

// ---------------- scratch (device globals; no allocation) ----------------
__device__ float          g_maxiou[Nn * Aa];
__device__ unsigned char  g_assigned[Nn * Aa];
__device__ unsigned char  g_posovr[Nn * Aa];

__device__ int            g_nvalid[Nn];
__device__ float4         g_vbox[Nn * Tt];
__device__ float          g_varea[Nn * Tt];
__device__ unsigned char  g_vt[Nn * Tt];
__device__ unsigned char  g_label[Nn * Tt];

__device__ int            g_gtbest[Nn * Tt];
__device__ unsigned char  g_lq[Nn * Tt];

__device__ int            g_poscnt[Nn];
__device__ float          g_pcls[NBLK];
__device__ float          g_pbox[NBLK];

// ---------------- K0: setup (labels, valid-row compaction, zeroing) ----------------
__global__ void k0_setup(const float* __restrict__ y_true,
                         const float* __restrict__ bbox_true) {
    int tid = threadIdx.x;
    if (tid < Nn) g_poscnt[tid] = 0;

    // labels: argmax over C of one-hot y_true rows
    for (int r = tid; r < Nn * Tt; r += blockDim.x) {
        const float* row = y_true + (size_t)r * Cc;
        int best = 0; float bv = row[0];
        for (int c = 1; c < Cc; c++) {
            float v = row[c];
            if (v > bv) { bv = v; best = c; }
        }
        g_label[r] = (unsigned char)best;
    }
    __syncthreads();

    // compact valid GT rows per image
    if (tid < Nn) {
        int n = tid, k = 0;
        for (int t = 0; t < Tt; t++) {
            const float* b = bbox_true + ((size_t)n * Tt + t) * 4;
            float x1 = b[0], y1 = b[1], x2 = b[2], y2 = b[3];
            bool valid = (x1 > 0.f) || (y1 > 0.f) || (x2 > 0.f) || (y2 > 0.f);
            if (valid) {
                g_vbox[n * Tt + k]  = make_float4(x1, y1, x2, y2);
                g_varea[n * Tt + k] = fmaxf(x2 - x1, 0.f) * fmaxf(y2 - y1, 0.f);
                g_vt[n * Tt + k]    = (unsigned char)t;
                k++;
            }
        }
        g_nvalid[n] = k;
    }
}

// ---------------- K1: per-anchor max_iou / assigned over valid GT rows ----------------
__global__ void k1_anchor(const float4* __restrict__ anchors) {
    int n = blockIdx.y;
    __shared__ float4 sbox[Tt];
    __shared__ float  sarea[Tt];
    __shared__ unsigned char svt[Tt];
    int nv = g_nvalid[n];
    for (int i = threadIdx.x; i < nv; i += blockDim.x) {
        sbox[i]  = g_vbox[n * Tt + i];
        sarea[i] = g_varea[n * Tt + i];
        svt[i]   = g_vt[n * Tt + i];
    }
    __syncthreads();

    int a = blockIdx.x * blockDim.x + threadIdx.x;
    float4 an = anchors[a];
    float a2 = fmaxf(an.z - an.x, 0.f) * fmaxf(an.w - an.y, 0.f);

    float best = -1.0f; int arg = 0;
    for (int k = 0; k < nv; k++) {
        float4 b = sbox[k];
        float lx = fmaxf(b.x, an.x), ly = fmaxf(b.y, an.y);
        float rx = fminf(b.z, an.z), ry = fminf(b.w, an.w);
        float iw = fmaxf(rx - lx, 0.f), ih = fmaxf(ry - ly, 0.f);
        float inter = iw * ih;
        float uni = sarea[k] + a2 - inter;
        float iou = inter / fmaxf(uni, 1e-10f);
        if (iou > best) { best = iou; arg = svt[k]; }   // first-max semantics
    }
    size_t idx = (size_t)n * Aa + a;
    g_maxiou[idx]   = best;
    g_assigned[idx] = (unsigned char)arg;
    g_posovr[idx]   = 0;
}

// ---------------- K2: per-GT best anchor (argmax over A, first-index tie-break) ----------------
__global__ void k2_gtbest(const float4* __restrict__ anchors,
                          const float* __restrict__ bbox_true) {
    int b = blockIdx.x;          // n*Tt + t
    const float* bt = bbox_true + (size_t)b * 4;
    float x1 = bt[0], y1 = bt[1], x2 = bt[2], y2 = bt[3];
    bool valid = (x1 > 0.f) || (y1 > 0.f) || (x2 > 0.f) || (y2 > 0.f);
    if (!valid) {
        if (threadIdx.x == 0) { g_lq[b] = 0; g_gtbest[b] = 0; }
        return;
    }
    float a1 = fmaxf(x2 - x1, 0.f) * fmaxf(y2 - y1, 0.f);

    unsigned long long bestkey = 0ull;
    for (int a = threadIdx.x; a < Aa; a += blockDim.x) {
        float4 an = anchors[a];
        float a2 = fmaxf(an.z - an.x, 0.f) * fmaxf(an.w - an.y, 0.f);
        float lx = fmaxf(x1, an.x), ly = fmaxf(y1, an.y);
        float rx = fminf(x2, an.z), ry = fminf(y2, an.w);
        float iw = fmaxf(rx - lx, 0.f), ih = fmaxf(ry - ly, 0.f);
        float inter = iw * ih;
        float uni = a1 + a2 - inter;
        float iou = inter / fmaxf(uni, 1e-10f);
        // iou >= 0 -> float bits monotone as unsigned; ~a breaks ties toward smaller a
        unsigned long long key =
            ((unsigned long long)__float_as_uint(iou) << 32) |
            (unsigned long long)(0xFFFFFFFFu - (unsigned)a);
        if (key > bestkey) bestkey = key;
    }
    __shared__ unsigned long long sk[256];
    sk[threadIdx.x] = bestkey;
    __syncthreads();
    for (int s = 128; s > 0; s >>= 1) {
        if (threadIdx.x < s) {
            unsigned long long o = sk[threadIdx.x + s];
            if (o > sk[threadIdx.x]) sk[threadIdx.x] = o;
        }
        __syncthreads();
    }
    if (threadIdx.x == 0) {
        unsigned long long k = sk[0];
        float bi = __uint_as_float((unsigned)(k >> 32));
        int ba = (int)(0xFFFFFFFFu - (unsigned)(k & 0xFFFFFFFFull));
        g_gtbest[b] = ba;
        g_lq[b] = (bi > 0.0f) ? 1 : 0;
    }
}

// ---------------- K3: low-quality match overrides (sequential t, last wins) ----------------
__global__ void k3_lq() {
    int n = threadIdx.x;
    if (n >= Nn) return;
    for (int t = 0; t < Tt; t++) {
        int b = n * Tt + t;
        if (g_lq[b]) {
            int a = g_gtbest[b];
            size_t idx = (size_t)n * Aa + a;
            g_assigned[idx] = (unsigned char)t;
            g_posovr[idx]   = 1;
        }
    }
}

// ---------------- K4: main loss (focal BCE + smooth L1), coalesced float4 over y_pred ----------------
__global__ void k4_loss(const float* __restrict__ y_pred,
                        const float4* __restrict__ bbox_pred,
                        const float4* __restrict__ anchors,
                        const float* __restrict__ bbox_true) {
    int n = blockIdx.y;
    int f = blockIdx.x * blockDim.x + threadIdx.x;   // float4 index within image n
    int a = f / 20;
    int cpart = f - a * 20;                          // which group of 4 classes
    size_t aidx = (size_t)n * Aa + a;

    float mi = g_maxiou[aidx];
    int ovr = g_posovr[aidx];
    bool pos = (mi >= 0.5f) || (ovr != 0);
    bool neg = (mi < 0.4f) && !pos;

    float clsl = 0.f, boxl = 0.f;

    if (pos || neg) {
        int label = -1;
        int asg = 0;
        if (pos) {
            asg = g_assigned[aidx];
            label = g_label[n * Tt + asg];
        }
        const float4* yp = (const float4*)y_pred + (size_t)n * NFLT4;
        float4 v = yp[f];
        float l4[4] = {v.x, v.y, v.z, v.w};
        int cbase = cpart * 4;
        #pragma unroll
        for (int j = 0; j < 4; j++) {
            float lg = l4[j];
            float em = __expf(-fabsf(lg));       // exp(-|l|) in (0,1]
            float u  = 1.0f + em;
            float lu = __logf(u);                // softplus(-|l|)
            float inv_u = __frcp_rn(u);
            bool y1 = pos && ((cbase + j) == label);
            float loss;
            if (y1) {
                // q = 1-p ; ce = softplus(-l)
                float q  = (lg >= 0.f) ? em * inv_u : inv_u;
                float ce = (lg >= 0.f) ? lu : (lu - lg);
                loss = F_ALPHA * q * q * ce;
            } else {
                // p = sigmoid(l) ; ce = softplus(l)
                float p  = (lg >= 0.f) ? inv_u : em * inv_u;
                float ce = (lg >= 0.f) ? (lg + lu) : lu;
                loss = (1.0f - F_ALPHA) * p * p * ce;
            }
            clsl += loss;
        }

        if (cpart == 0 && pos) {
            atomicAdd(&g_poscnt[n], 1);
            float4 an = anchors[a];
            float4 bp = bbox_pred[aidx];
            const float* bt = bbox_true + ((size_t)n * Tt + asg) * 4;
            float bx1 = bt[0], by1 = bt[1], bx2 = bt[2], by2 = bt[3];
            float wa = fmaxf(an.z - an.x, F_EPS);
            float ha = fmaxf(an.w - an.y, F_EPS);
            float cxa = an.x + 0.5f * wa;
            float cya = an.y + 0.5f * ha;
            float wt = fmaxf(bx2 - bx1, F_EPS);
            float ht = fmaxf(by2 - by1, F_EPS);
            float cxt = bx1 + 0.5f * (bx2 - bx1);
            float cyt = by1 + 0.5f * (by2 - by1);
            float d0 = (cxt - cxa) / wa;
            float d1 = (cyt - cya) / ha;
            float d2 = logf(wt / wa);
            float d3 = logf(ht / ha);
            float pr[4] = {bp.x, bp.y, bp.z, bp.w};
            float tg[4] = {d0, d1, d2, d3};
            #pragma unroll
            for (int j = 0; j < 4; j++) {
                float d = fabsf(tg[j] - pr[j]);
                boxl += (d < SL1_BETA) ? (0.5f * d * d / SL1_BETA)
                                       : (d - 0.5f * SL1_BETA);
            }
        }
    }

    // block reduction (warp shuffle then shared)
    unsigned full = 0xFFFFFFFFu;
    #pragma unroll
    for (int o = 16; o > 0; o >>= 1) {
        clsl += __shfl_down_sync(full, clsl, o);
        boxl += __shfl_down_sync(full, boxl, o);
    }
    __shared__ float wc[8], wb[8];
    int w = threadIdx.x >> 5, lane = threadIdx.x & 31;
    if (lane == 0) { wc[w] = clsl; wb[w] = boxl; }
    __syncthreads();
    if (threadIdx.x == 0) {
        float c = 0.f, b = 0.f;
        #pragma unroll
        for (int i = 0; i < 8; i++) { c += wc[i]; b += wb[i]; }
        int bid = blockIdx.y * gridDim.x + blockIdx.x;
        g_pcls[bid] = c;
        g_pbox[bid] = b;
    }
}

// ---------------- K5: final reduce + normalize + sanitize ----------------
__global__ void k5_final(float* __restrict__ out) {
    __shared__ double sc[256], sb[256];
    int tid = threadIdx.x;
    double c = 0.0, b = 0.0;
    for (int i = tid; i < NBLK; i += 256) {
        c += (double)g_pcls[i];
        b += (double)g_pbox[i];
    }
    sc[tid] = c; sb[tid] = b;
    __syncthreads();
    for (int s = 128; s > 0; s >>= 1) {
        if (tid < s) { sc[tid] += sc[tid + s]; sb[tid] += sb[tid + s]; }
        __syncthreads();
    }
    if (tid == 0) {
        double avg = 0.0;
        for (int n = 0; n < Nn; n++) {
            double p = (double)g_poscnt[n];
            avg += (p > 1.0) ? p : 1.0;
        }
        float cls = (float)(sc[0] / avg);
        float box = (float)(sb[0] / avg);
        if (isnan(cls) || isinf(cls)) cls = 0.f;
        if (isnan(box) || isinf(box)) box = 0.f;
        out[0] = cls;
        out[1] = box;
    }
}

// ---------------- launch ----------------
extern "C" void kernel_launch(void* const* d_in, const int* in_sizes, int n_in,
                              void* d_out, int out_size) {
    const float*  y_true    = (const float*)d_in[0];
    const float*  bbox_true = (const float*)d_in[1];
    const float*  y_pred    = (const float*)d_in[2];
    const float4* bbox_pred = (const float4*)d_in[3];
    const float4* anchors   = (const float4*)d_in[4];
    float* out = (float*)d_out;

    k0_setup<<<1, 256>>>(y_true, bbox_true);
    k1_anchor<<<dim3(Aa / 256, Nn), 256>>>(anchors);
    k2_gtbest<<<Nn * Tt, 256>>>(anchors, bbox_true);
    k3_lq<<<1, 32>>>();
    k4_loss<<<dim3(K4_BLOCKS_X, Nn), 256>>>(y_pred, bbox_pred, anchors,
                                            (const float*)d_in[1]);
    k5_final<<<1, 256>>>(out);
}

// round 2
// speedup vs baseline: 1.3540x; 1.3540x over previous
#include <cuda_runtime.h>
#include <math.h>

#define Nn 8
#define Tt 64
#define Aa 65536
#define Cc 80
#define NFLT4 (Aa * (Cc / 4))          // float4s of y_pred per batch image = 1,310,720
#define K4_BLOCKS_X (NFLT4 / 256)      // 5120
#define NBLK (K4_BLOCKS_X * Nn)        // 40960

#define F_ALPHA 0.25f
#define F_EPS 1e-6f
#define SL1_BETA (1.0f / 9.0f)

// ---------------- scratch (device globals; no allocation) ----------------
__device__ float          g_maxiou[Nn * Aa];
__device__ int            g_asg[Nn * Aa];    // [30]=override flag, low bits = gt index t

__device__ int            g_nvalid[Nn];
__device__ float4         g_vbox[Nn * Tt];
__device__ float          g_varea[Nn * Tt];
__device__ unsigned char  g_vt[Nn * Tt];
__device__ unsigned char  g_label[Nn * Tt];

__device__ unsigned long long g_gtkey[Nn * Tt];   // (iou_bits<<32) | ~anchor

__device__ int            g_poscnt[Nn];
__device__ float          g_pcls[NBLK];
__device__ float          g_pbox[NBLK];

// ---------------- K0: setup (labels, valid-row compaction, init) ----------------
__global__ void k0_setup(const float* __restrict__ y_true,
                         const float* __restrict__ bbox_true) {
    int tid = threadIdx.x;
    if (tid < Nn) g_poscnt[tid] = 0;
    for (int i = tid; i < Nn * Tt; i += blockDim.x) g_gtkey[i] = 0ull;

    // labels: argmax over C of one-hot y_true rows
    for (int r = tid; r < Nn * Tt; r += blockDim.x) {
        const float* row = y_true + (size_t)r * Cc;
        int best = 0; float bv = row[0];
        for (int c = 1; c < Cc; c++) {
            float v = row[c];
            if (v > bv) { bv = v; best = c; }
        }
        g_label[r] = (unsigned char)best;
    }
    __syncthreads();

    // compact valid GT rows per image
    if (tid < Nn) {
        int n = tid, k = 0;
        for (int t = 0; t < Tt; t++) {
            const float* b = bbox_true + ((size_t)n * Tt + t) * 4;
            float x1 = b[0], y1 = b[1], x2 = b[2], y2 = b[3];
            bool valid = (x1 > 0.f) || (y1 > 0.f) || (x2 > 0.f) || (y2 > 0.f);
            if (valid) {
                g_vbox[n * Tt + k]  = make_float4(x1, y1, x2, y2);
                g_varea[n * Tt + k] = fmaxf(x2 - x1, 0.f) * fmaxf(y2 - y1, 0.f);
                g_vt[n * Tt + k]    = (unsigned char)t;
                k++;
            }
        }
        g_nvalid[n] = k;
    }
}

// ---------------- K1: fused per-anchor max_iou/assigned + per-GT best anchor ----------------
__global__ void k1_anchor(const float4* __restrict__ anchors) {
    int n = blockIdx.y;
    __shared__ float4 sbox[Tt];
    __shared__ float  sarea[Tt];
    __shared__ unsigned char svt[Tt];
    __shared__ unsigned long long skey[Tt];
    int nv = g_nvalid[n];
    for (int i = threadIdx.x; i < nv; i += blockDim.x) {
        sbox[i]  = g_vbox[n * Tt + i];
        sarea[i] = g_varea[n * Tt + i];
        svt[i]   = g_vt[n * Tt + i];
    }
    if (threadIdx.x < Tt) skey[threadIdx.x] = 0ull;
    __syncthreads();

    int a = blockIdx.x * blockDim.x + threadIdx.x;
    float4 an = anchors[a];
    float a2 = fmaxf(an.z - an.x, 0.f) * fmaxf(an.w - an.y, 0.f);
    unsigned lane = threadIdx.x & 31;

    float best = -1.0f; int arg = 0;
    for (int k = 0; k < nv; k++) {
        float4 b = sbox[k];
        float lx = fmaxf(b.x, an.x), ly = fmaxf(b.y, an.y);
        float rx = fminf(b.z, an.z), ry = fminf(b.w, an.w);
        float iw = fmaxf(rx - lx, 0.f), ih = fmaxf(ry - ly, 0.f);
        float inter = iw * ih;
        float uni = sarea[k] + a2 - inter;
        float iou = inter / fmaxf(uni, 1e-10f);       // exact div: thresholds are flip-sensitive
        if (iou > best) { best = iou; arg = svt[k]; } // first-max semantics (smallest t)

        // per-gt best anchor: warp reduce of packed key, then shared atomic
        unsigned long long key =
            ((unsigned long long)__float_as_uint(iou) << 32) |
            (unsigned long long)(~(unsigned)a);       // smaller a wins ties
        #pragma unroll
        for (int o = 16; o > 0; o >>= 1) {
            unsigned long long other = __shfl_down_sync(0xFFFFFFFFu, key, o);
            if (other > key) key = other;
        }
        if (lane == 0) atomicMax(&skey[k], key);
    }
    __syncthreads();

    size_t idx = (size_t)n * Aa + a;
    g_maxiou[idx] = best;
    g_asg[idx]    = arg;
    if (threadIdx.x < nv)
        atomicMax(&g_gtkey[n * Tt + threadIdx.x], skey[threadIdx.x]);
}

// ---------------- K2: low-quality overrides (parallel; largest t wins = last-wins) ----------------
__global__ void k2_lq() {
    int idx = threadIdx.x;               // 512 threads = Nn*Tt
    int n = idx >> 6, k = idx & 63;
    if (k < g_nvalid[n]) {
        unsigned long long key = g_gtkey[n * Tt + k];
        float iou = __uint_as_float((unsigned)(key >> 32));
        if (iou > 0.0f) {
            int a = (int)(~(unsigned)(key & 0xFFFFFFFFull));
            int t = g_vt[n * Tt + k];
            atomicMax(&g_asg[(size_t)n * Aa + a], 0x40000000 | t);
        }
    }
}

// ---------------- K3: main loss (focal BCE + smooth L1), coalesced float4 over y_pred ----------------
__global__ void k3_loss(const float* __restrict__ y_pred,
                        const float4* __restrict__ bbox_pred,
                        const float4* __restrict__ anchors,
                        const float* __restrict__ bbox_true) {
    int n = blockIdx.y;
    int f = blockIdx.x * blockDim.x + threadIdx.x;   // float4 index within image n
    int a = f / 20;
    int cpart = f - a * 20;                          // group of 4 classes
    size_t aidx = (size_t)n * Aa + a;

    float mi = g_maxiou[aidx];
    int v = g_asg[aidx];
    bool ovr = (v & 0x40000000) != 0;
    bool pos = ovr || (mi >= 0.5f);
    bool neg = (mi < 0.4f) && !pos;

    float clsl = 0.f, boxl = 0.f;

    if (pos || neg) {
        int asg = ovr ? (v & 0xFF) : v;
        int label = pos ? (int)g_label[n * Tt + asg] : -1;

        const float4* yp = (const float4*)y_pred + (size_t)n * NFLT4;
        float4 vv = yp[f];
        float l4[4] = {vv.x, vv.y, vv.z, vv.w};
        int cbase = cpart * 4;
        #pragma unroll
        for (int j = 0; j < 4; j++) {
            float lg = l4[j];
            float em = __expf(-fabsf(lg));
            float u  = 1.0f + em;
            float lu = __logf(u);
            float inv_u = __frcp_rn(u);
            bool y1 = (cbase + j) == label;
            float loss;
            if (y1) {
                float q  = (lg >= 0.f) ? em * inv_u : inv_u;     // 1-p
                float ce = (lg >= 0.f) ? lu : (lu - lg);          // softplus(-l)
                loss = F_ALPHA * q * q * ce;
            } else {
                float p  = (lg >= 0.f) ? inv_u : em * inv_u;      // p
                float ce = (lg >= 0.f) ? (lg + lu) : lu;          // softplus(l)
                loss = (1.0f - F_ALPHA) * p * p * ce;
            }
            clsl += loss;
        }

        if (cpart == 0 && pos) {
            atomicAdd(&g_poscnt[n], 1);
            float4 an = anchors[a];
            float4 bp = bbox_pred[aidx];
            const float* bt = bbox_true + ((size_t)n * Tt + asg) * 4;
            float bx1 = bt[0], by1 = bt[1], bx2 = bt[2], by2 = bt[3];
            float wa = fmaxf(an.z - an.x, F_EPS);
            float ha = fmaxf(an.w - an.y, F_EPS);
            float cxa = an.x + 0.5f * wa;
            float cya = an.y + 0.5f * ha;
            float wt = fmaxf(bx2 - bx1, F_EPS);
            float ht = fmaxf(by2 - by1, F_EPS);
            float cxt = bx1 + 0.5f * (bx2 - bx1);
            float cyt = by1 + 0.5f * (by2 - by1);
            float tg[4] = {(cxt - cxa) / wa, (cyt - cya) / ha,
                           logf(wt / wa),    logf(ht / ha)};
            float pr[4] = {bp.x, bp.y, bp.z, bp.w};
            #pragma unroll
            for (int j = 0; j < 4; j++) {
                float d = fabsf(tg[j] - pr[j]);
                boxl += (d < SL1_BETA) ? (0.5f * d * d / SL1_BETA)
                                       : (d - 0.5f * SL1_BETA);
            }
        }
    }

    // block reduction
    unsigned full = 0xFFFFFFFFu;
    #pragma unroll
    for (int o = 16; o > 0; o >>= 1) {
        clsl += __shfl_down_sync(full, clsl, o);
        boxl += __shfl_down_sync(full, boxl, o);
    }
    __shared__ float wc[8], wb[8];
    int w = threadIdx.x >> 5, lane = threadIdx.x & 31;
    if (lane == 0) { wc[w] = clsl; wb[w] = boxl; }
    __syncthreads();
    if (threadIdx.x == 0) {
        float c = 0.f, b = 0.f;
        #pragma unroll
        for (int i = 0; i < 8; i++) { c += wc[i]; b += wb[i]; }
        int bid = blockIdx.y * gridDim.x + blockIdx.x;
        g_pcls[bid] = c;
        g_pbox[bid] = b;
    }
}

// ---------------- K4: final reduce + normalize + sanitize ----------------
__global__ void k4_final(float* __restrict__ out) {
    __shared__ double sc[256], sb[256];
    int tid = threadIdx.x;
    double c = 0.0, b = 0.0;
    for (int i = tid; i < NBLK; i += 256) {
        c += (double)g_pcls[i];
        b += (double)g_pbox[i];
    }
    sc[tid] = c; sb[tid] = b;
    __syncthreads();
    for (int s = 128; s > 0; s >>= 1) {
        if (tid < s) { sc[tid] += sc[tid + s]; sb[tid] += sb[tid + s]; }
        __syncthreads();
    }
    if (tid == 0) {
        double avg = 0.0;
        for (int n = 0; n < Nn; n++) {
            double p = (double)g_poscnt[n];
            avg += (p > 1.0) ? p : 1.0;
        }
        float cls = (float)(sc[0] / avg);
        float box = (float)(sb[0] / avg);
        if (isnan(cls) || isinf(cls)) cls = 0.f;
        if (isnan(box) || isinf(box)) box = 0.f;
        out[0] = cls;
        out[1] = box;
    }
}

// ---------------- launch ----------------
extern "C" void kernel_launch(void* const* d_in, const int* in_sizes, int n_in,
                              void* d_out, int out_size) {
    const float*  y_true    = (const float*)d_in[0];
    const float*  bbox_true = (const float*)d_in[1];
    const float*  y_pred    = (const float*)d_in[2];
    const float4* bbox_pred = (const float4*)d_in[3];
    const float4* anchors   = (const float4*)d_in[4];
    float* out = (float*)d_out;

    k0_setup<<<1, 256>>>(y_true, bbox_true);
    k1_anchor<<<dim3(Aa / 256, Nn), 256>>>(anchors);
    k2_lq<<<1, Nn * Tt>>>();
    k3_loss<<<dim3(K4_BLOCKS_X, Nn), 256>>>(y_pred, bbox_pred, anchors, bbox_true);
    k4_final<<<1, 256>>>(out);
}

// round 3
// speedup vs baseline: 1.7123x; 1.2646x over previous
#include <cuda_runtime.h>
#include <math.h>

#define Nn 8
#define Tt 64
#define Aa 65536
#define Cc 80
#define NFLT4 (Aa * (Cc / 4))          // float4s of y_pred per image = 1,310,720
#define K3_BLOCKS_X (NFLT4 / 256)      // 5120
#define NBLK (K3_BLOCKS_X * Nn)        // 40960

#define F_EPS 1e-6f
#define SL1_BETA (1.0f / 9.0f)
#define LN2 0.69314718055994531f

// ---------------- scratch (device globals; no allocation) ----------------
__device__ float          g_maxiou[Nn * Aa];
__device__ int            g_asg[Nn * Aa];    // bit30 = override, low bits = gt index t

__device__ int            g_nvalid[Nn];
__device__ float4         g_vbox[Nn * Tt];
__device__ float          g_varea[Nn * Tt];
__device__ unsigned char  g_vt[Nn * Tt];
__device__ unsigned char  g_label[Nn * Tt];

__device__ unsigned long long g_gtkey[Nn * Tt];   // (iou_bits<<32) | ~anchor

__device__ int            g_poscnt[Nn];
__device__ float          g_pcls[NBLK];
__device__ float          g_pbox[NBLK];

__device__ __forceinline__ float rcp_approx(float x) {
    float r;
    asm("rcp.approx.f32 %0, %1;" : "=f"(r) : "f"(x));
    return r;
}

// ---------------- K0: setup (labels, valid-row compaction, init) ----------------
__global__ void k0_setup(const float* __restrict__ y_true,
                         const float* __restrict__ bbox_true) {
    __shared__ float4 sb[Nn * Tt];     // 8 KB
    int tid = threadIdx.x;
    if (tid < Nn) g_poscnt[tid] = 0;
    for (int i = tid; i < Nn * Tt; i += 256) {
        g_gtkey[i] = 0ull;
        sb[i] = ((const float4*)bbox_true)[i];   // coalesced stage
    }

    // labels: locate the 1.0 in each one-hot row (float4 loads)
    for (int r = tid; r < Nn * Tt; r += 256) {
        const float4* row = (const float4*)(y_true + (size_t)r * Cc);
        int lab = 0;
        #pragma unroll 4
        for (int q = 0; q < Cc / 4; q++) {
            float4 v = row[q];
            if (v.x > 0.5f) lab = 4 * q;
            if (v.y > 0.5f) lab = 4 * q + 1;
            if (v.z > 0.5f) lab = 4 * q + 2;
            if (v.w > 0.5f) lab = 4 * q + 3;
        }
        g_label[r] = (unsigned char)lab;
    }
    __syncthreads();

    // compact valid GT rows per image (from smem — no latency chain)
    if (tid < Nn) {
        int n = tid, k = 0;
        for (int t = 0; t < Tt; t++) {
            float4 b = sb[n * Tt + t];
            bool valid = (b.x > 0.f) || (b.y > 0.f) || (b.z > 0.f) || (b.w > 0.f);
            if (valid) {
                g_vbox[n * Tt + k]  = b;
                g_varea[n * Tt + k] = fmaxf(b.z - b.x, 0.f) * fmaxf(b.w - b.y, 0.f);
                g_vt[n * Tt + k]    = (unsigned char)t;
                k++;
            }
        }
        g_nvalid[n] = k;
    }
}

// ---------------- K1: fused per-anchor max_iou/assigned + per-GT best anchor ----------------
__global__ void k1_anchor(const float4* __restrict__ anchors) {
    int n = blockIdx.y;
    __shared__ float4 sbox[Tt];
    __shared__ float  sarea[Tt];
    __shared__ unsigned char svt[Tt];
    __shared__ unsigned long long swkey[8][Tt];   // per-warp per-gt best key
    int nv = g_nvalid[n];
    for (int i = threadIdx.x; i < nv; i += blockDim.x) {
        sbox[i]  = g_vbox[n * Tt + i];
        sarea[i] = g_varea[n * Tt + i];
        svt[i]   = g_vt[n * Tt + i];
    }
    __syncthreads();

    int a = blockIdx.x * blockDim.x + threadIdx.x;
    float4 an = anchors[a];
    float a2 = fmaxf(an.z - an.x, 0.f) * fmaxf(an.w - an.y, 0.f);
    unsigned lane = threadIdx.x & 31;
    int w = threadIdx.x >> 5;

    float best = -1.0f; int arg = 0;
    for (int k = 0; k < nv; k++) {
        float4 b = sbox[k];
        float lx = fmaxf(b.x, an.x), ly = fmaxf(b.y, an.y);
        float rx = fminf(b.z, an.z), ry = fminf(b.w, an.w);
        float iw = fmaxf(rx - lx, 0.f), ih = fmaxf(ry - ly, 0.f);
        float inter = iw * ih;
        float uni = sarea[k] + a2 - inter;
        float iou = inter / fmaxf(uni, 1e-10f);       // exact div: thresholds flip-sensitive
        if (iou > best) { best = iou; arg = svt[k]; } // first-max (smallest t)

        // warp argmax via redux + ballot; lowest lane = smallest anchor id
        unsigned ib = __float_as_uint(iou);           // iou >= 0 -> bits monotone
        unsigned mx = __reduce_max_sync(0xFFFFFFFFu, ib);
        unsigned msk = __ballot_sync(0xFFFFFFFFu, ib == mx);
        if (lane == (unsigned)(__ffs(msk) - 1))
            swkey[w][k] = ((unsigned long long)mx << 32) |
                          (unsigned long long)(~(unsigned)a);
    }
    __syncthreads();

    size_t idx = (size_t)n * Aa + a;
    g_maxiou[idx] = best;
    g_asg[idx]    = arg;

    if (threadIdx.x < nv) {
        unsigned long long m = swkey[0][threadIdx.x];
        #pragma unroll
        for (int ww = 1; ww < 8; ww++) {
            unsigned long long o = swkey[ww][threadIdx.x];
            if (o > m) m = o;
        }
        if ((m >> 32) != 0)   // iou == 0 can't produce an override anyway
            atomicMax(&g_gtkey[n * Tt + threadIdx.x], m);
    }
}

// ---------------- K2: low-quality overrides (largest t wins = last-wins) ----------------
__global__ void k2_lq() {
    int idx = threadIdx.x;               // 512 threads = Nn*Tt
    int n = idx >> 6, k = idx & 63;
    if (k < g_nvalid[n]) {
        unsigned long long key = g_gtkey[n * Tt + k];
        float iou = __uint_as_float((unsigned)(key >> 32));
        if (iou > 0.0f) {
            int a = (int)(~(unsigned)(key & 0xFFFFFFFFull));
            int t = g_vt[n * Tt + k];
            atomicMax(&g_asg[(size_t)n * Aa + a], 0x40000000 | t);
        }
    }
}

// ---------------- K3: main loss. Uniform neg-focal per element + rare pos correction ----------------
__global__ void k3_loss(const float* __restrict__ y_pred,
                        const float4* __restrict__ bbox_pred,
                        const float4* __restrict__ anchors,
                        const float* __restrict__ bbox_true) {
    int n = blockIdx.y;
    int f = blockIdx.x * blockDim.x + threadIdx.x;   // float4 index within image n
    int a = f / 20;
    int cpart = f - a * 20;                          // group of 4 classes
    size_t aidx = (size_t)n * Aa + a;

    float mi = g_maxiou[aidx];
    int v = g_asg[aidx];
    bool ovr = (v & 0x40000000) != 0;
    bool pos = ovr || (mi >= 0.5f);
    bool tw  = pos || (mi < 0.4f);

    float clsl = 0.f, boxl = 0.f;

    if (tw) {
        const float4* yp = (const float4*)y_pred + (size_t)n * NFLT4;
        float4 vv = yp[f];
        float l4[4] = {vv.x, vv.y, vv.z, vv.w};
        float S = 0.f;
        #pragma unroll
        for (int j = 0; j < 4; j++) {
            float l  = l4[j];
            float m  = fabsf(l);
            float em = __expf(-m);                   // FMUL + MUFU.EX2
            float u  = 1.0f + em;
            float lg = __log2f(u);                   // MUFU.LG2
            float r  = rcp_approx(u);                // MUFU.RCP
            float p  = (l >= 0.f) ? r : em * r;      // sigmoid(l)
            float ce = fmaf(lg, LN2, fmaxf(l, 0.f)); // softplus(l)
            S = fmaf(p * p, ce, S);
        }
        clsl = 0.75f * S;

        if (pos) {
            int asg = ovr ? (v & 0xFF) : v;
            int label = (int)g_label[n * Tt + asg];
            int j = label - cpart * 4;
            if (j >= 0 && j < 4) {                   // correct the label element
                float l  = l4[j];
                float m  = fabsf(l);
                float em = __expf(-m);
                float u  = 1.0f + em;
                float lv = __log2f(u) * LN2;
                float r  = rcp_approx(u);
                float p  = (l >= 0.f) ? r : em * r;
                float q  = 1.0f - p;
                float ce_pos = lv + fmaxf(-l, 0.f);  // softplus(-l)
                float ce_neg = lv + fmaxf(l, 0.f);   // softplus(l)
                clsl += 0.25f * q * q * ce_pos - 0.75f * p * p * ce_neg;
            }
            if (cpart == 0) {
                atomicAdd(&g_poscnt[n], 1);
                float4 an = anchors[a];
                float4 bp = bbox_pred[aidx];
                const float* bt = bbox_true + ((size_t)n * Tt + asg) * 4;
                float bx1 = bt[0], by1 = bt[1], bx2 = bt[2], by2 = bt[3];
                float wa = fmaxf(an.z - an.x, F_EPS);
                float ha = fmaxf(an.w - an.y, F_EPS);
                float cxa = an.x + 0.5f * wa;
                float cya = an.y + 0.5f * ha;
                float wt = fmaxf(bx2 - bx1, F_EPS);
                float ht = fmaxf(by2 - by1, F_EPS);
                float cxt = bx1 + 0.5f * (bx2 - bx1);
                float cyt = by1 + 0.5f * (by2 - by1);
                float tg[4] = {(cxt - cxa) / wa, (cyt - cya) / ha,
                               logf(wt / wa),    logf(ht / ha)};
                float pr[4] = {bp.x, bp.y, bp.z, bp.w};
                #pragma unroll
                for (int jj = 0; jj < 4; jj++) {
                    float d = fabsf(tg[jj] - pr[jj]);
                    boxl += (d < SL1_BETA) ? (0.5f * d * d / SL1_BETA)
                                           : (d - 0.5f * SL1_BETA);
                }
            }
        }
    }

    // block reduction
    unsigned full = 0xFFFFFFFFu;
    #pragma unroll
    for (int o = 16; o > 0; o >>= 1) {
        clsl += __shfl_down_sync(full, clsl, o);
        boxl += __shfl_down_sync(full, boxl, o);
    }
    __shared__ float wc[8], wb[8];
    int w = threadIdx.x >> 5, lane = threadIdx.x & 31;
    if (lane == 0) { wc[w] = clsl; wb[w] = boxl; }
    __syncthreads();
    if (threadIdx.x == 0) {
        float c = 0.f, b = 0.f;
        #pragma unroll
        for (int i = 0; i < 8; i++) { c += wc[i]; b += wb[i]; }
        int bid = blockIdx.y * gridDim.x + blockIdx.x;
        g_pcls[bid] = c;
        g_pbox[bid] = b;
    }
}

// ---------------- K4: final reduce + normalize + sanitize ----------------
__global__ void k4_final(float* __restrict__ out) {
    __shared__ double sc[256], sb[256];
    int tid = threadIdx.x;
    double c = 0.0, b = 0.0;
    for (int i = tid; i < NBLK; i += 256) {
        c += (double)g_pcls[i];
        b += (double)g_pbox[i];
    }
    sc[tid] = c; sb[tid] = b;
    __syncthreads();
    for (int s = 128; s > 0; s >>= 1) {
        if (tid < s) { sc[tid] += sc[tid + s]; sb[tid] += sb[tid + s]; }
        __syncthreads();
    }
    if (tid == 0) {
        double avg = 0.0;
        for (int n = 0; n < Nn; n++) {
            double p = (double)g_poscnt[n];
            avg += (p > 1.0) ? p : 1.0;
        }
        float cls = (float)(sc[0] / avg);
        float box = (float)(sb[0] / avg);
        if (isnan(cls) || isinf(cls)) cls = 0.f;
        if (isnan(box) || isinf(box)) box = 0.f;
        out[0] = cls;
        out[1] = box;
    }
}

// ---------------- launch ----------------
extern "C" void kernel_launch(void* const* d_in, const int* in_sizes, int n_in,
                              void* d_out, int out_size) {
    const float*  y_true    = (const float*)d_in[0];
    const float*  bbox_true = (const float*)d_in[1];
    const float*  y_pred    = (const float*)d_in[2];
    const float4* bbox_pred = (const float4*)d_in[3];
    const float4* anchors   = (const float4*)d_in[4];
    float* out = (float*)d_out;

    k0_setup<<<1, 256>>>(y_true, bbox_true);
    k1_anchor<<<dim3(Aa / 256, Nn), 256>>>(anchors);
    k2_lq<<<1, Nn * Tt>>>();
    k3_loss<<<dim3(K3_BLOCKS_X, Nn), 256>>>(y_pred, bbox_pred, anchors, bbox_true);
    k4_final<<<1, 256>>>(out);
}

// round 4
// speedup vs baseline: 2.0891x; 1.2200x over previous
#include <cuda_runtime.h>
#include <math.h>

#define Nn 8
#define Tt 64
#define Aa 65536
#define Cc 80
#define NFLT4 (Aa * (Cc / 4))          // float4s of y_pred per image = 1,310,720
#define K3_BLOCKS_X (NFLT4 / 512)      // 2560 (each thread: 2 float4s)
#define NBLK (K3_BLOCKS_X * Nn)        // 20480

#define F_EPS 1e-6f
#define SL1_BETA (1.0f / 9.0f)
#define LN2 0.69314718055994531f

// ---------------- scratch (device globals; no allocation) ----------------
__device__ unsigned char  g_state[Nn * Aa];  // 0=ignore 1=neg 2=pos
__device__ int            g_asg[Nn * Aa];    // bit30 = override, low bits = gt index t

__device__ int            g_nvalid[Nn];
__device__ float4         g_vbox[Nn * Tt];
__device__ float          g_varea[Nn * Tt];
__device__ unsigned char  g_vt[Nn * Tt];
__device__ unsigned char  g_label[Nn * Tt];

__device__ unsigned long long g_gtkey[Nn * Tt];   // (iou_bits<<32) | ~anchor

__device__ int            g_poscnt[Nn];
__device__ float          g_pcls[NBLK];
__device__ float          g_pbox[NBLK];

__device__ __forceinline__ float rcp_approx(float x) {
    float r;
    asm("rcp.approx.f32 %0, %1;" : "=f"(r) : "f"(x));
    return r;
}

// ---------------- K0a: labels + zero-init (2 blocks x 256) ----------------
__global__ void k0a_labels(const float* __restrict__ y_true) {
    int tid = threadIdx.x;
    if (blockIdx.x == 0) {
        if (tid < Nn) g_poscnt[tid] = 0;
        for (int i = tid; i < Nn * Tt; i += 256) g_gtkey[i] = 0ull;
    }
    int r = blockIdx.x * 256 + tid;          // one one-hot row per thread
    const float4* row = (const float4*)(y_true + (size_t)r * Cc);
    int lab = 0;
    #pragma unroll 4
    for (int q = 0; q < Cc / 4; q++) {
        float4 v = row[q];
        if (v.x > 0.5f) lab = 4 * q;
        if (v.y > 0.5f) lab = 4 * q + 1;
        if (v.z > 0.5f) lab = 4 * q + 2;
        if (v.w > 0.5f) lab = 4 * q + 3;
    }
    g_label[r] = (unsigned char)lab;
}

// ---------------- K0b: valid-row compaction (1 block) ----------------
__global__ void k0b_compact(const float* __restrict__ bbox_true) {
    __shared__ float4 sb[Nn * Tt];     // 8 KB staged coalesced
    int tid = threadIdx.x;
    for (int i = tid; i < Nn * Tt; i += 256)
        sb[i] = ((const float4*)bbox_true)[i];
    __syncthreads();
    if (tid < Nn) {
        int n = tid, k = 0;
        for (int t = 0; t < Tt; t++) {
            float4 b = sb[n * Tt + t];
            bool valid = (b.x > 0.f) || (b.y > 0.f) || (b.z > 0.f) || (b.w > 0.f);
            if (valid) {
                g_vbox[n * Tt + k]  = b;
                g_varea[n * Tt + k] = fmaxf(b.z - b.x, 0.f) * fmaxf(b.w - b.y, 0.f);
                g_vt[n * Tt + k]    = (unsigned char)t;
                k++;
            }
        }
        g_nvalid[n] = k;
    }
}

// ---------------- K1: per-anchor state/assigned + per-GT best anchor ----------------
__global__ void k1_anchor(const float4* __restrict__ anchors) {
    int n = blockIdx.y;
    __shared__ float4 sbox[Tt];
    __shared__ float  sarea[Tt];
    __shared__ unsigned char svt[Tt];
    __shared__ unsigned long long swkey[8][Tt];   // per-warp per-gt best key
    int nv = g_nvalid[n];
    for (int i = threadIdx.x; i < nv; i += blockDim.x) {
        sbox[i]  = g_vbox[n * Tt + i];
        sarea[i] = g_varea[n * Tt + i];
        svt[i]   = g_vt[n * Tt + i];
    }
    __syncthreads();

    int a = blockIdx.x * blockDim.x + threadIdx.x;
    float4 an = anchors[a];
    float a2 = fmaxf(an.z - an.x, 0.f) * fmaxf(an.w - an.y, 0.f);
    unsigned lane = threadIdx.x & 31;
    int w = threadIdx.x >> 5;

    float best = -1.0f; int arg = 0;
    for (int k = 0; k < nv; k++) {
        float4 b = sbox[k];
        float lx = fmaxf(b.x, an.x), ly = fmaxf(b.y, an.y);
        float rx = fminf(b.z, an.z), ry = fminf(b.w, an.w);
        float iw = fmaxf(rx - lx, 0.f), ih = fmaxf(ry - ly, 0.f);
        float inter = iw * ih;
        float uni = sarea[k] + a2 - inter;
        float iou = inter / fmaxf(uni, 1e-10f);       // exact div: thresholds flip-sensitive
        if (iou > best) { best = iou; arg = svt[k]; } // first-max (smallest t)

        unsigned ib = __float_as_uint(iou);           // iou >= 0 -> bits monotone
        unsigned mx = __reduce_max_sync(0xFFFFFFFFu, ib);
        unsigned msk = __ballot_sync(0xFFFFFFFFu, ib == mx);
        if (lane == (unsigned)(__ffs(msk) - 1))
            swkey[w][k] = ((unsigned long long)mx << 32) |
                          (unsigned long long)(~(unsigned)a);
    }
    __syncthreads();

    size_t idx = (size_t)n * Aa + a;
    g_asg[idx]   = arg;
    g_state[idx] = (best >= 0.5f) ? 2 : ((best < 0.4f) ? 1 : 0);

    if (threadIdx.x < nv) {
        unsigned long long m = swkey[0][threadIdx.x];
        #pragma unroll
        for (int ww = 1; ww < 8; ww++) {
            unsigned long long o = swkey[ww][threadIdx.x];
            if (o > m) m = o;
        }
        if ((m >> 32) != 0)
            atomicMax(&g_gtkey[n * Tt + threadIdx.x], m);
    }
}

// ---------------- K2: low-quality overrides (largest t wins = last-wins) ----------------
__global__ void k2_lq() {
    int idx = threadIdx.x;               // 512 threads = Nn*Tt
    int n = idx >> 6, k = idx & 63;
    if (k < g_nvalid[n]) {
        unsigned long long key = g_gtkey[n * Tt + k];
        float iou = __uint_as_float((unsigned)(key >> 32));
        if (iou > 0.0f) {
            int a = (int)(~(unsigned)(key & 0xFFFFFFFFull));
            int t = g_vt[n * Tt + k];
            size_t p = (size_t)n * Aa + a;
            atomicMax(&g_asg[p], 0x40000000 | t);
            g_state[p] = 2;
        }
    }
}

// ---------------- K3: main loss. state-byte gated; 8 elems/thread ----------------
__global__ void k3_loss(const float* __restrict__ y_pred,
                        const float4* __restrict__ bbox_pred,
                        const float4* __restrict__ anchors,
                        const float* __restrict__ bbox_true) {
    int n = blockIdx.y;
    const float4* yp = (const float4*)y_pred + (size_t)n * NFLT4;
    const unsigned char* st_n = g_state + (size_t)n * Aa;

    float clsl = 0.f, boxl = 0.f;

    #pragma unroll
    for (int half = 0; half < 2; half++) {
        int f = blockIdx.x * 512 + half * 256 + threadIdx.x;
        int a = f / 20;
        int cpart = f - a * 20;
        unsigned st = st_n[a];
        if (st == 0) continue;

        float4 vv = yp[f];
        float l4[4] = {vv.x, vv.y, vv.z, vv.w};
        float p4[4], ce4[4];
        float S = 0.f;
        #pragma unroll
        for (int j = 0; j < 4; j++) {
            float l  = l4[j];
            float t  = __expf(-fabsf(l));            // FMUL + MUFU.EX2
            float u  = 1.0f + t;
            float r  = rcp_approx(u);                // MUFU.RCP
            float lg = __log2f(u);                   // MUFU.LG2
            float p  = (l >= 0.f) ? r : t * r;       // sigmoid(l)
            float ce = fmaf(lg, LN2, fmaxf(l, 0.f)); // softplus(l)
            p4[j] = p; ce4[j] = ce;
            S = fmaf(p * p, ce, S);
        }
        clsl = fmaf(0.75f, S, clsl);

        if (st == 2) {                               // positive anchor (rare)
            size_t aidx = (size_t)n * Aa + a;
            int v = g_asg[aidx];
            int asg = (v & 0x40000000) ? (v & 0xFF) : v;
            int j = (int)g_label[n * Tt + asg] - cpart * 4;
            if (j >= 0 && j < 4) {
                float p = p4[j], ce = ce4[j], l = l4[j];
                float q = 1.0f - p;
                // + alpha*q^2*sp(-l) - (1-alpha)*p^2*sp(l);  sp(-l) = ce - l
                clsl += 0.25f * q * q * (ce - l) - 0.75f * p * p * ce;
            }
            if (cpart == 0) {
                atomicAdd(&g_poscnt[n], 1);
                float4 an = anchors[a];
                float4 bp = bbox_pred[aidx];
                const float* bt = bbox_true + ((size_t)n * Tt + asg) * 4;
                float bx1 = bt[0], by1 = bt[1], bx2 = bt[2], by2 = bt[3];
                float wa = fmaxf(an.z - an.x, F_EPS);
                float ha = fmaxf(an.w - an.y, F_EPS);
                float cxa = an.x + 0.5f * wa;
                float cya = an.y + 0.5f * ha;
                float wt = fmaxf(bx2 - bx1, F_EPS);
                float ht = fmaxf(by2 - by1, F_EPS);
                float cxt = bx1 + 0.5f * (bx2 - bx1);
                float cyt = by1 + 0.5f * (by2 - by1);
                float tg[4] = {(cxt - cxa) / wa, (cyt - cya) / ha,
                               logf(wt / wa),    logf(ht / ha)};
                float pr[4] = {bp.x, bp.y, bp.z, bp.w};
                #pragma unroll
                for (int jj = 0; jj < 4; jj++) {
                    float d = fabsf(tg[jj] - pr[jj]);
                    boxl += (d < SL1_BETA) ? (0.5f * d * d / SL1_BETA)
                                           : (d - 0.5f * SL1_BETA);
                }
            }
        }
    }

    // block reduction
    unsigned full = 0xFFFFFFFFu;
    #pragma unroll
    for (int o = 16; o > 0; o >>= 1) {
        clsl += __shfl_down_sync(full, clsl, o);
        boxl += __shfl_down_sync(full, boxl, o);
    }
    __shared__ float wc[8], wb[8];
    int w = threadIdx.x >> 5, lane = threadIdx.x & 31;
    if (lane == 0) { wc[w] = clsl; wb[w] = boxl; }
    __syncthreads();
    if (threadIdx.x == 0) {
        float c = 0.f, b = 0.f;
        #pragma unroll
        for (int i = 0; i < 8; i++) { c += wc[i]; b += wb[i]; }
        int bid = blockIdx.y * gridDim.x + blockIdx.x;
        g_pcls[bid] = c;
        g_pbox[bid] = b;
    }
}

// ---------------- K4: final reduce + normalize + sanitize ----------------
__global__ void k4_final(float* __restrict__ out) {
    __shared__ double sc[256], sb[256];
    int tid = threadIdx.x;
    double c = 0.0, b = 0.0;
    for (int i = tid; i < NBLK; i += 256) {
        c += (double)g_pcls[i];
        b += (double)g_pbox[i];
    }
    sc[tid] = c; sb[tid] = b;
    __syncthreads();
    for (int s = 128; s > 0; s >>= 1) {
        if (tid < s) { sc[tid] += sc[tid + s]; sb[tid] += sb[tid + s]; }
        __syncthreads();
    }
    if (tid == 0) {
        double avg = 0.0;
        for (int n = 0; n < Nn; n++) {
            double p = (double)g_poscnt[n];
            avg += (p > 1.0) ? p : 1.0;
        }
        float cls = (float)(sc[0] / avg);
        float box = (float)(sb[0] / avg);
        if (isnan(cls) || isinf(cls)) cls = 0.f;
        if (isnan(box) || isinf(box)) box = 0.f;
        out[0] = cls;
        out[1] = box;
    }
}

// ---------------- launch ----------------
extern "C" void kernel_launch(void* const* d_in, const int* in_sizes, int n_in,
                              void* d_out, int out_size) {
    const float*  y_true    = (const float*)d_in[0];
    const float*  bbox_true = (const float*)d_in[1];
    const float*  y_pred    = (const float*)d_in[2];
    const float4* bbox_pred = (const float4*)d_in[3];
    const float4* anchors   = (const float4*)d_in[4];
    float* out = (float*)d_out;

    k0a_labels<<<2, 256>>>(y_true);
    k0b_compact<<<1, 256>>>(bbox_true);
    k1_anchor<<<dim3(Aa / 256, Nn), 256>>>(anchors);
    k2_lq<<<1, Nn * Tt>>>();
    k3_loss<<<dim3(K3_BLOCKS_X, Nn), 256>>>(y_pred, bbox_pred, anchors, bbox_true);
    k4_final<<<1, 256>>>(out);
}

// round 5
// speedup vs baseline: 2.6976x; 1.2913x over previous
#include <cuda_runtime.h>
#include <math.h>

#define Nn 8
#define Tt 64
#define Aa 65536
#define Cc 80
#define NFLT4 (Aa * (Cc / 4))          // float4s of y_pred per image = 1,310,720
#define ITER 8                          // float4s per thread in k3
#define K3BX (NFLT4 / (256 * ITER))     // 640 blocks per image
#define NBLK (K3BX * Nn)                // 5120 partials
#define K1_BLOCKS ((Aa / 256) * Nn)     // 2048

#define F_EPS 1e-6f
#define SL1_BETA (1.0f / 9.0f)
#define LN2 0.69314718055994531f

// ---------------- scratch (device globals; no allocation) ----------------
__device__ unsigned char  g_state[Nn * Aa];  // 0=ignore 1=neg 2=pos
__device__ int            g_asg[Nn * Aa];    // bit30 = override, low bits = gt index t

__device__ int            g_nvalid[Nn];
__device__ float4         g_vbox[Nn * Tt];
__device__ float          g_varea[Nn * Tt];
__device__ unsigned char  g_vt[Nn * Tt];
__device__ unsigned char  g_label[Nn * Tt];

__device__ unsigned long long g_gtkey[Nn * Tt];   // (iou_bits<<32) | ~anchor

__device__ int            g_poscnt[Nn];
__device__ float          g_pcls[NBLK];
__device__ float          g_pbox[NBLK];

__device__ unsigned       g_done1;
__device__ unsigned       g_done3;

__device__ __forceinline__ float rcp_approx(float x) {
    float r;
    asm("rcp.approx.f32 %0, %1;" : "=f"(r) : "f"(x));
    return r;
}

// ---------------- K0: labels + compaction + resets (3 blocks) ----------------
__global__ void k0_setup(const float* __restrict__ y_true,
                         const float* __restrict__ bbox_true) {
    int tid = threadIdx.x;
    if (blockIdx.x < 2) {
        int r = blockIdx.x * 256 + tid;          // one one-hot row per thread
        const float4* row = (const float4*)(y_true + (size_t)r * Cc);
        int lab = 0;
        #pragma unroll 4
        for (int q = 0; q < Cc / 4; q++) {
            float4 v = row[q];
            if (v.x > 0.5f) lab = 4 * q;
            if (v.y > 0.5f) lab = 4 * q + 1;
            if (v.z > 0.5f) lab = 4 * q + 2;
            if (v.w > 0.5f) lab = 4 * q + 3;
        }
        g_label[r] = (unsigned char)lab;
        return;
    }
    // block 2: resets + valid-row compaction
    __shared__ float4 sb[Nn * Tt];     // 8 KB staged coalesced
    if (tid == 0) { g_done1 = 0; g_done3 = 0; }
    if (tid < Nn) g_poscnt[tid] = 0;
    for (int i = tid; i < Nn * Tt; i += 256) {
        g_gtkey[i] = 0ull;
        sb[i] = ((const float4*)bbox_true)[i];
    }
    __syncthreads();
    if (tid < Nn) {
        int n = tid, k = 0;
        for (int t = 0; t < Tt; t++) {
            float4 b = sb[n * Tt + t];
            bool valid = (b.x > 0.f) || (b.y > 0.f) || (b.z > 0.f) || (b.w > 0.f);
            if (valid) {
                g_vbox[n * Tt + k]  = b;
                g_varea[n * Tt + k] = fmaxf(b.z - b.x, 0.f) * fmaxf(b.w - b.y, 0.f);
                g_vt[n * Tt + k]    = (unsigned char)t;
                k++;
            }
        }
        g_nvalid[n] = k;
    }
}

// ---------------- K1: per-anchor state/assigned + per-GT best + fused LQ tail ----------------
__global__ void k1_anchor(const float4* __restrict__ anchors) {
    int n = blockIdx.y;
    __shared__ float4 sbox[Tt];
    __shared__ float  sarea[Tt];
    __shared__ unsigned char svt[Tt];
    __shared__ unsigned long long swkey[8][Tt];
    int nv = g_nvalid[n];
    for (int i = threadIdx.x; i < nv; i += blockDim.x) {
        sbox[i]  = g_vbox[n * Tt + i];
        sarea[i] = g_varea[n * Tt + i];
        svt[i]   = g_vt[n * Tt + i];
    }
    __syncthreads();

    int a = blockIdx.x * blockDim.x + threadIdx.x;
    float4 an = anchors[a];
    float a2 = fmaxf(an.z - an.x, 0.f) * fmaxf(an.w - an.y, 0.f);
    unsigned lane = threadIdx.x & 31;
    int w = threadIdx.x >> 5;

    float best = -1.0f; int arg = 0;
    for (int k = 0; k < nv; k++) {
        float4 b = sbox[k];
        float lx = fmaxf(b.x, an.x), ly = fmaxf(b.y, an.y);
        float rx = fminf(b.z, an.z), ry = fminf(b.w, an.w);
        float iw = fmaxf(rx - lx, 0.f), ih = fmaxf(ry - ly, 0.f);
        float inter = iw * ih;
        float uni = sarea[k] + a2 - inter;
        float iou = inter / fmaxf(uni, 1e-10f);       // exact div: thresholds flip-sensitive
        if (iou > best) { best = iou; arg = svt[k]; } // first-max (smallest t)

        unsigned ib = __float_as_uint(iou);           // iou >= 0 -> bits monotone
        unsigned mx = __reduce_max_sync(0xFFFFFFFFu, ib);
        unsigned msk = __ballot_sync(0xFFFFFFFFu, ib == mx);
        if (lane == (unsigned)(__ffs(msk) - 1))
            swkey[w][k] = ((unsigned long long)mx << 32) |
                          (unsigned long long)(~(unsigned)a);
    }
    __syncthreads();

    size_t idx = (size_t)n * Aa + a;
    g_asg[idx]   = arg;
    g_state[idx] = (best >= 0.5f) ? 2 : ((best < 0.4f) ? 1 : 0);

    if (threadIdx.x < nv) {
        unsigned long long m = swkey[0][threadIdx.x];
        #pragma unroll
        for (int ww = 1; ww < 8; ww++) {
            unsigned long long o = swkey[ww][threadIdx.x];
            if (o > m) m = o;
        }
        if ((m >> 32) != 0)
            atomicMax(&g_gtkey[n * Tt + threadIdx.x], m);
    }

    // --- fused low-quality override: last finishing block applies all ---
    __syncthreads();
    __threadfence();
    __shared__ bool slast;
    if (threadIdx.x == 0)
        slast = (atomicAdd(&g_done1, 1u) == (unsigned)(K1_BLOCKS - 1));
    __syncthreads();
    if (slast) {
        for (int idx2 = threadIdx.x; idx2 < Nn * Tt; idx2 += 256) {
            int nn = idx2 >> 6, k = idx2 & 63;
            if (k < g_nvalid[nn]) {
                unsigned long long key = g_gtkey[nn * Tt + k];
                if ((key >> 32) != 0) {               // best iou > 0
                    int aa = (int)(~(unsigned)(key & 0xFFFFFFFFull));
                    int t = g_vt[nn * Tt + k];
                    size_t p = (size_t)nn * Aa + aa;
                    atomicMax(&g_asg[p], 0x40000000 | t);
                    g_state[p] = 2;
                }
            }
        }
    }
}

// ---------------- K3: main loss (branch-free neg path) + fused final reduce ----------------
__global__ void k3_loss(const float* __restrict__ y_pred,
                        const float4* __restrict__ bbox_pred,
                        const float4* __restrict__ anchors,
                        const float* __restrict__ bbox_true,
                        float* __restrict__ out) {
    int n = blockIdx.y;
    const float4* yp = (const float4*)y_pred + (size_t)n * NFLT4;
    const unsigned char* st_n = g_state + (size_t)n * Aa;

    float clsl = 0.f, boxl = 0.f;
    int base = blockIdx.x * (256 * ITER);

    #pragma unroll
    for (int i = 0; i < ITER; i++) {
        int f = base + i * 256 + threadIdx.x;
        int a = f / 20;
        int cpart = f - a * 20;
        unsigned st = st_n[a];

        float4 vv = yp[f];
        float l4[4] = {vv.x, vv.y, vv.z, vv.w};
        float p4[4], ce4[4];
        float S = 0.f;
        #pragma unroll
        for (int j = 0; j < 4; j++) {
            float l  = l4[j];
            float t  = __expf(-fabsf(l));            // FMUL + MUFU.EX2
            float u  = 1.0f + t;
            float r  = rcp_approx(u);                // MUFU.RCP
            float lg = __log2f(u);                   // MUFU.LG2
            float p  = (l >= 0.f) ? r : t * r;       // sigmoid(l)
            float ce = fmaf(lg, LN2, fmaxf(l, 0.f)); // softplus(l)
            p4[j] = p; ce4[j] = ce;
            S = fmaf(p * p, ce, S);
        }
        float w = (st != 0) ? 0.75f : 0.0f;
        clsl = fmaf(w, S, clsl);

        if (st == 2) {                               // positive anchor (rare)
            size_t aidx = (size_t)n * Aa + a;
            int v = g_asg[aidx];
            int asg = (v & 0x40000000) ? (v & 0xFF) : v;
            int j = (int)g_label[n * Tt + asg] - cpart * 4;
            if (j >= 0 && j < 4) {
                float p = p4[j], ce = ce4[j], l = l4[j];
                float q = 1.0f - p;
                // + alpha*q^2*sp(-l) - (1-alpha)*p^2*sp(l);  sp(-l) = ce - l
                clsl += 0.25f * q * q * (ce - l) - 0.75f * p * p * ce;
            }
            if (cpart == 0) {
                atomicAdd(&g_poscnt[n], 1);
                float4 an = anchors[a];
                float4 bp = bbox_pred[aidx];
                const float* bt = bbox_true + ((size_t)n * Tt + asg) * 4;
                float bx1 = bt[0], by1 = bt[1], bx2 = bt[2], by2 = bt[3];
                float wa = fmaxf(an.z - an.x, F_EPS);
                float ha = fmaxf(an.w - an.y, F_EPS);
                float cxa = an.x + 0.5f * wa;
                float cya = an.y + 0.5f * ha;
                float wt = fmaxf(bx2 - bx1, F_EPS);
                float ht = fmaxf(by2 - by1, F_EPS);
                float cxt = bx1 + 0.5f * (bx2 - bx1);
                float cyt = by1 + 0.5f * (by2 - by1);
                float tg[4] = {(cxt - cxa) / wa, (cyt - cya) / ha,
                               logf(wt / wa),    logf(ht / ha)};
                float pr[4] = {bp.x, bp.y, bp.z, bp.w};
                #pragma unroll
                for (int jj = 0; jj < 4; jj++) {
                    float d = fabsf(tg[jj] - pr[jj]);
                    boxl += (d < SL1_BETA) ? (0.5f * d * d / SL1_BETA)
                                           : (d - 0.5f * SL1_BETA);
                }
            }
        }
    }

    // block reduction
    unsigned full = 0xFFFFFFFFu;
    #pragma unroll
    for (int o = 16; o > 0; o >>= 1) {
        clsl += __shfl_down_sync(full, clsl, o);
        boxl += __shfl_down_sync(full, boxl, o);
    }
    __shared__ float wc[8], wb[8];
    int w = threadIdx.x >> 5, lane = threadIdx.x & 31;
    if (lane == 0) { wc[w] = clsl; wb[w] = boxl; }
    __syncthreads();
    if (threadIdx.x == 0) {
        float c = 0.f, b = 0.f;
        #pragma unroll
        for (int i = 0; i < 8; i++) { c += wc[i]; b += wb[i]; }
        int bid = blockIdx.y * gridDim.x + blockIdx.x;
        g_pcls[bid] = c;
        g_pbox[bid] = b;
    }

    // --- fused final reduction: last finishing block ---
    __syncthreads();
    __threadfence();
    __shared__ bool slast;
    if (threadIdx.x == 0)
        slast = (atomicAdd(&g_done3, 1u) == (unsigned)(NBLK - 1));
    __syncthreads();
    if (!slast) return;

    __shared__ double sc[256], sb2[256];
    int tid = threadIdx.x;
    double c = 0.0, b = 0.0;
    for (int i = tid; i < NBLK; i += 256) {
        c += (double)g_pcls[i];
        b += (double)g_pbox[i];
    }
    sc[tid] = c; sb2[tid] = b;
    __syncthreads();
    for (int s = 128; s > 0; s >>= 1) {
        if (tid < s) { sc[tid] += sc[tid + s]; sb2[tid] += sb2[tid + s]; }
        __syncthreads();
    }
    if (tid == 0) {
        double avg = 0.0;
        for (int nn = 0; nn < Nn; nn++) {
            double p = (double)g_poscnt[nn];
            avg += (p > 1.0) ? p : 1.0;
        }
        float cls = (float)(sc[0] / avg);
        float box = (float)(sb2[0] / avg);
        if (isnan(cls) || isinf(cls)) cls = 0.f;
        if (isnan(box) || isinf(box)) box = 0.f;
        out[0] = cls;
        out[1] = box;
    }
}

// ---------------- launch ----------------
extern "C" void kernel_launch(void* const* d_in, const int* in_sizes, int n_in,
                              void* d_out, int out_size) {
    const float*  y_true    = (const float*)d_in[0];
    const float*  bbox_true = (const float*)d_in[1];
    const float*  y_pred    = (const float*)d_in[2];
    const float4* bbox_pred = (const float4*)d_in[3];
    const float4* anchors   = (const float4*)d_in[4];
    float* out = (float*)d_out;

    k0_setup<<<3, 256>>>(y_true, bbox_true);
    k1_anchor<<<dim3(Aa / 256, Nn), 256>>>(anchors);
    k3_loss<<<dim3(K3BX, Nn), 256>>>(y_pred, bbox_pred, anchors, bbox_true, out);
}

// round 6
// speedup vs baseline: 2.7170x; 1.0072x over previous
#include <cuda_runtime.h>
#include <math.h>

#define Nn 8
#define Tt 64
#define Aa 65536
#define Cc 80
#define NFLT4 (Aa * (Cc / 4))          // float4s of y_pred per image = 1,310,720
#define ITER 8                          // float4s per thread in k3
#define K3BX (NFLT4 / (256 * ITER))     // 640 blocks per image
#define NBLK (K3BX * Nn)                // 5120 partials
#define K1_BLOCKS ((Aa / 256) * Nn)     // 2048

#define F_EPS 1e-6f
#define SL1_BETA (1.0f / 9.0f)
#define LN2 0.69314718055994531f

// ---------------- scratch (device globals; no allocation) ----------------
__device__ unsigned char  g_state[Nn * Aa];  // 0=ignore 1=neg 2=pos
__device__ int            g_asg[Nn * Aa];    // bit30 = override, low bits = gt index t
__device__ int            g_nvalid[Nn];
__device__ unsigned char  g_vt[Nn * Tt];
__device__ unsigned char  g_label[Nn * Tt];
__device__ unsigned long long g_gtkey[Nn * Tt];   // (iou_bits<<32) | ~anchor
__device__ int            g_poscnt[Nn];
__device__ float          g_pcls[NBLK];
__device__ float          g_pbox[NBLK];
__device__ unsigned       g_done1;
__device__ unsigned       g_done3;

// ---------------- helpers ----------------
__device__ __forceinline__ float rcp_approx(float x) {
    float r; asm("rcp.approx.f32 %0, %1;" : "=f"(r) : "f"(x)); return r;
}
__device__ __forceinline__ float ex2a(float x) {
    float r; asm("ex2.approx.f32 %0, %1;" : "=f"(r) : "f"(x)); return r;
}
__device__ __forceinline__ float lg2a(float x) {
    float r; asm("lg2.approx.f32 %0, %1;" : "=f"(r) : "f"(x)); return r;
}
__device__ __forceinline__ float slctf(float a, float b, float c) {
    float r; asm("slct.f32.f32 %0, %1, %2, %3;" : "=f"(r) : "f"(a), "f"(b), "f"(c)); return r;
}
#define PK(d, a, b)    asm("mov.b64 %0, {%1, %2};" : "=l"(d) : "f"(a), "f"(b))
#define UPK(a, b, s)   asm("mov.b64 {%0, %1}, %2;" : "=f"(a), "=f"(b) : "l"(s))
#define F2MUL(d, a, b) asm("mul.rn.f32x2 %0, %1, %2;" : "=l"(d) : "l"(a), "l"(b))
#define F2ADD(d, a, b) asm("add.rn.f32x2 %0, %1, %2;" : "=l"(d) : "l"(a), "l"(b))
#define F2FMA(d, a, b, c) asm("fma.rn.f32x2 %0, %1, %2, %3;" : "=l"(d) : "l"(a), "l"(b), "l"(c))

struct PackK {
    unsigned long long SGN, ONE, TWO, M3, C3, C2, C1, C0;
};

// sum of p^2*softplus(l) over a packed pair; 2 MUFU + packed FMA work
__device__ __forceinline__ float pair_focal(float la, float lb, const PackK& K) {
    float t0 = ex2a(fabsf(la) * -1.44269504f);   // e^{-|l|}
    float t1 = ex2a(fabsf(lb) * -1.44269504f);
    unsigned long long T, U, X, R, NU, E, W, T2, V;
    PK(T, t0, t1);
    F2ADD(U, T, K.ONE);                          // u = 1 + t  in (1,2]
    float u0, u1; UPK(u0, u1, U);
    float lga = lg2a(u0), lgb = lg2a(u1);        // log2(u)
    F2FMA(X, U, K.TWO, K.M3);                    // x = 2u - 3 in [-1,1]
    F2FMA(R, K.C3, X, K.C2);                     // cubic seed for 1/u
    F2FMA(R, R, X, K.C1);
    F2FMA(R, R, X, K.C0);
    asm("xor.b64 %0, %1, %2;" : "=l"(NU) : "l"(U), "l"(K.SGN));
    F2FMA(E, NU, R, K.TWO);                      // 2 - u*r  (Newton)
    F2MUL(R, R, E);                              // r1 ~ 1/u  (rel err ~2e-6)
    F2MUL(W, R, R);                              // 1/u^2 = p^2 for l>=0
    F2MUL(T2, T, T);
    F2MUL(V, T2, W);                             // t^2/u^2 = p^2 for l<0
    float w0, w1, v0, v1;
    UPK(w0, w1, W); UPK(v0, v1, V);
    float p20 = slctf(w0, v0, la);
    float p21 = slctf(w1, v1, lb);
    float ce0 = fmaf(lga, (float)LN2, fmaxf(la, 0.f));   // softplus(l)
    float ce1 = fmaf(lgb, (float)LN2, fmaxf(lb, 0.f));
    return fmaf(p20, ce0, p21 * ce1);
}

// ---------------- K1: compaction + per-anchor state/assigned + per-GT best + LQ tail ----------------
__global__ void k1_anchor(const float4* __restrict__ anchors,
                          const float4* __restrict__ bb,
                          const float* __restrict__ y_true) {
    int n = blockIdx.y;
    __shared__ float4 sbox[Tt];
    __shared__ float  sarea[Tt];
    __shared__ unsigned char svt[Tt];
    __shared__ unsigned long long swkey[8][Tt];
    __shared__ unsigned smask[2];
    __shared__ int snv;
    int tid = threadIdx.x;

    // block-local compaction of valid GT rows (ballot prefix over 2 warps)
    float4 myb; bool myvalid = false; unsigned mk = 0;
    if (tid < 64) {
        myb = bb[n * Tt + tid];
        myvalid = (myb.x > 0.f) || (myb.y > 0.f) || (myb.z > 0.f) || (myb.w > 0.f);
        mk = __ballot_sync(0xFFFFFFFFu, myvalid);
        if ((tid & 31) == 0) smask[tid >> 5] = mk;
    }
    // labels (only 8 blocks do this; needed by k3 later)
    if (blockIdx.x == 0 && tid >= 64 && tid < 128) {
        int r = n * Tt + (tid - 64);
        const float4* row = (const float4*)(y_true + (size_t)r * Cc);
        int lab = 0;
        #pragma unroll 4
        for (int q = 0; q < Cc / 4; q++) {
            float4 v = row[q];
            if (v.x > 0.5f) lab = 4 * q;
            if (v.y > 0.5f) lab = 4 * q + 1;
            if (v.z > 0.5f) lab = 4 * q + 2;
            if (v.w > 0.5f) lab = 4 * q + 3;
        }
        g_label[r] = (unsigned char)lab;
    }
    __syncthreads();
    if (tid < 64 && myvalid) {
        int pos = __popc(mk & ((1u << (tid & 31)) - 1)) +
                  ((tid >= 32) ? __popc(smask[0]) : 0);
        sbox[pos]  = myb;
        sarea[pos] = fmaxf(myb.z - myb.x, 0.f) * fmaxf(myb.w - myb.y, 0.f);
        svt[pos]   = (unsigned char)tid;
        if (blockIdx.x == 0) g_vt[n * Tt + pos] = (unsigned char)tid;
    }
    if (tid == 0) {
        snv = __popc(smask[0]) + __popc(smask[1]);
        if (blockIdx.x == 0) g_nvalid[n] = snv;
    }
    __syncthreads();
    int nv = snv;

    int a = blockIdx.x * blockDim.x + tid;
    float4 an = anchors[a];
    float a2 = fmaxf(an.z - an.x, 0.f) * fmaxf(an.w - an.y, 0.f);
    unsigned lane = tid & 31;
    int w = tid >> 5;

    float best = -1.0f; int arg = 0;
    for (int k = 0; k < nv; k++) {
        float4 b = sbox[k];
        float lx = fmaxf(b.x, an.x), ly = fmaxf(b.y, an.y);
        float rx = fminf(b.z, an.z), ry = fminf(b.w, an.w);
        float iw = fmaxf(rx - lx, 0.f), ih = fmaxf(ry - ly, 0.f);
        float inter = iw * ih;
        float uni = sarea[k] + a2 - inter;
        float iou = inter / fmaxf(uni, 1e-10f);       // exact div: thresholds flip-sensitive
        if (iou > best) { best = iou; arg = svt[k]; } // first-max (smallest t)

        unsigned ib = __float_as_uint(iou);           // iou >= 0 -> bits monotone
        unsigned mx = __reduce_max_sync(0xFFFFFFFFu, ib);
        unsigned msk = __ballot_sync(0xFFFFFFFFu, ib == mx);
        if (lane == (unsigned)(__ffs(msk) - 1))
            swkey[w][k] = ((unsigned long long)mx << 32) |
                          (unsigned long long)(~(unsigned)a);
    }
    __syncthreads();

    size_t idx = (size_t)n * Aa + a;
    g_asg[idx]   = arg;
    g_state[idx] = (best >= 0.5f) ? 2 : ((best < 0.4f) ? 1 : 0);

    if (tid < nv) {
        unsigned long long m = swkey[0][tid];
        #pragma unroll
        for (int ww = 1; ww < 8; ww++) {
            unsigned long long o = swkey[ww][tid];
            if (o > m) m = o;
        }
        if ((m >> 32) != 0)
            atomicMax(&g_gtkey[n * Tt + tid], m);
    }

    // --- fused low-quality override: last finishing block applies all ---
    __syncthreads();
    __threadfence();
    __shared__ bool slast;
    if (tid == 0)
        slast = (atomicAdd(&g_done1, 1u) == (unsigned)(K1_BLOCKS - 1));
    __syncthreads();
    if (slast) {
        for (int idx2 = tid; idx2 < Nn * Tt; idx2 += 256) {
            int nn = idx2 >> 6, k = idx2 & 63;
            if (k < g_nvalid[nn]) {
                unsigned long long key = g_gtkey[nn * Tt + k];
                if ((key >> 32) != 0) {               // best iou > 0
                    int aa = (int)(~(unsigned)(key & 0xFFFFFFFFull));
                    int t = g_vt[nn * Tt + k];
                    size_t p = (size_t)nn * Aa + aa;
                    atomicMax(&g_asg[p], 0x40000000 | t);
                    g_state[p] = 2;
                }
            }
        }
    }
}

// ---------------- K3: main loss (packed f32x2, 2 MUFU/elem) + fused final reduce ----------------
__global__ void k3_loss(const float* __restrict__ y_pred,
                        const float4* __restrict__ bbox_pred,
                        const float4* __restrict__ anchors,
                        const float* __restrict__ bbox_true,
                        float* __restrict__ out) {
    int n = blockIdx.y;
    const float4* yp = (const float4*)y_pred + (size_t)n * NFLT4;
    const unsigned char* st_n = g_state + (size_t)n * Aa;

    PackK K;
    K.SGN = 0x8000000080000000ull;
    PK(K.ONE, 1.0f, 1.0f);
    PK(K.TWO, 2.0f, 2.0f);
    PK(K.M3, -3.0f, -3.0f);
    PK(K.C3, -0.028572f, -0.028572f);
    PK(K.C2,  0.08326f,   0.08326f);
    PK(K.C1, -0.22121f,  -0.22121f);
    PK(K.C0,  0.66548f,   0.66548f);

    float clsl = 0.f, boxl = 0.f;
    int base = blockIdx.x * (256 * ITER);

    #pragma unroll
    for (int i = 0; i < ITER; i++) {
        int f = base + i * 256 + threadIdx.x;
        int a = f / 20;
        int cpart = f - a * 20;
        unsigned st = st_n[a];

        float4 vv = yp[f];
        float S4 = pair_focal(vv.x, vv.y, K) + pair_focal(vv.z, vv.w, K);
        float wst = (st != 0) ? 0.75f : 0.0f;
        clsl = fmaf(wst, S4, clsl);

        if (st == 2) {                               // positive anchor (rare)
            size_t aidx = (size_t)n * Aa + a;
            int v = g_asg[aidx];
            int asg = (v & 0x40000000) ? (v & 0xFF) : v;
            int j = (int)g_label[n * Tt + asg] - cpart * 4;
            if (j >= 0 && j < 4) {                   // exact correction, no dynamic array
                float lsel = (j == 0) ? vv.x : ((j == 1) ? vv.y : ((j == 2) ? vv.z : vv.w));
                float mm = fabsf(lsel);
                float em = __expf(-mm);
                float uu = 1.0f + em;
                float r  = rcp_approx(uu);
                float lgv = __logf(uu);
                float p  = (lsel >= 0.f) ? r : em * r;
                float q  = 1.0f - p;
                float ce  = lgv + fmaxf(lsel, 0.f);   // softplus(l)
                float cep = lgv + fmaxf(-lsel, 0.f);  // softplus(-l)
                clsl += 0.25f * q * q * cep - 0.75f * p * p * ce;
            }
            if (cpart == 0) {
                atomicAdd(&g_poscnt[n], 1);
                float4 an = anchors[a];
                float4 bp = bbox_pred[aidx];
                const float* bt = bbox_true + ((size_t)n * Tt + asg) * 4;
                float bx1 = bt[0], by1 = bt[1], bx2 = bt[2], by2 = bt[3];
                float wa = fmaxf(an.z - an.x, F_EPS);
                float ha = fmaxf(an.w - an.y, F_EPS);
                float cxa = an.x + 0.5f * wa;
                float cya = an.y + 0.5f * ha;
                float wt = fmaxf(bx2 - bx1, F_EPS);
                float ht = fmaxf(by2 - by1, F_EPS);
                float cxt = bx1 + 0.5f * (bx2 - bx1);
                float cyt = by1 + 0.5f * (by2 - by1);
                float tg0 = (cxt - cxa) / wa;
                float tg1 = (cyt - cya) / ha;
                float tg2 = logf(wt / wa);
                float tg3 = logf(ht / ha);
                float d0 = fabsf(tg0 - bp.x), d1 = fabsf(tg1 - bp.y);
                float d2 = fabsf(tg2 - bp.z), d3 = fabsf(tg3 - bp.w);
                boxl += (d0 < SL1_BETA) ? (0.5f * d0 * d0 / SL1_BETA) : (d0 - 0.5f * SL1_BETA);
                boxl += (d1 < SL1_BETA) ? (0.5f * d1 * d1 / SL1_BETA) : (d1 - 0.5f * SL1_BETA);
                boxl += (d2 < SL1_BETA) ? (0.5f * d2 * d2 / SL1_BETA) : (d2 - 0.5f * SL1_BETA);
                boxl += (d3 < SL1_BETA) ? (0.5f * d3 * d3 / SL1_BETA) : (d3 - 0.5f * SL1_BETA);
            }
        }
    }

    // block reduction
    unsigned full = 0xFFFFFFFFu;
    #pragma unroll
    for (int o = 16; o > 0; o >>= 1) {
        clsl += __shfl_down_sync(full, clsl, o);
        boxl += __shfl_down_sync(full, boxl, o);
    }
    __shared__ float wc[8], wb[8];
    int w = threadIdx.x >> 5, lane = threadIdx.x & 31;
    if (lane == 0) { wc[w] = clsl; wb[w] = boxl; }
    __syncthreads();
    if (threadIdx.x == 0) {
        float c = 0.f, b = 0.f;
        #pragma unroll
        for (int i = 0; i < 8; i++) { c += wc[i]; b += wb[i]; }
        int bid = blockIdx.y * gridDim.x + blockIdx.x;
        g_pcls[bid] = c;
        g_pbox[bid] = b;
    }

    // --- fused final reduction: last finishing block ---
    __syncthreads();
    __threadfence();
    __shared__ bool slast;
    if (threadIdx.x == 0)
        slast = (atomicAdd(&g_done3, 1u) == (unsigned)(NBLK - 1));
    __syncthreads();
    if (!slast) return;

    __shared__ double sc[256], sb2[256];
    int tid = threadIdx.x;
    double c = 0.0, b = 0.0;
    for (int i = tid; i < NBLK; i += 256) {
        c += (double)g_pcls[i];
        b += (double)g_pbox[i];
    }
    sc[tid] = c; sb2[tid] = b;
    __syncthreads();
    for (int s = 128; s > 0; s >>= 1) {
        if (tid < s) { sc[tid] += sc[tid + s]; sb2[tid] += sb2[tid + s]; }
        __syncthreads();
    }
    if (tid == 0) {
        double avg = 0.0;
        for (int nn = 0; nn < Nn; nn++) {
            double p = (double)g_poscnt[nn];
            avg += (p > 1.0) ? p : 1.0;
        }
        float cls = (float)(sc[0] / avg);
        float box = (float)(sb2[0] / avg);
        if (isnan(cls) || isinf(cls)) cls = 0.f;
        if (isnan(box) || isinf(box)) box = 0.f;
        out[0] = cls;
        out[1] = box;
    }
    // resets for the next graph replay (after poscnt was consumed)
    __syncthreads();
    if (tid == 0) { g_done1 = 0; g_done3 = 0; }
    if (tid < Nn) g_poscnt[tid] = 0;
    for (int i = tid; i < Nn * Tt; i += 256) g_gtkey[i] = 0ull;
}

// ---------------- launch ----------------
extern "C" void kernel_launch(void* const* d_in, const int* in_sizes, int n_in,
                              void* d_out, int out_size) {
    const float*  y_true    = (const float*)d_in[0];
    const float*  bbox_true = (const float*)d_in[1];
    const float*  y_pred    = (const float*)d_in[2];
    const float4* bbox_pred = (const float4*)d_in[3];
    const float4* anchors   = (const float4*)d_in[4];
    float* out = (float*)d_out;

    k1_anchor<<<dim3(Aa / 256, Nn), 256>>>(anchors, (const float4*)bbox_true, y_true);
    k3_loss<<<dim3(K3BX, Nn), 256>>>(y_pred, bbox_pred, anchors, bbox_true, out);
}